// round 5
// baseline (speedup 1.0000x reference)
#include <cuda_runtime.h>
#include <math.h>

#define E_TOT 65536
#define NRELC 64
#define NSEG  2048      // B*N = 4*512
#define HIDC  768
#define NHEAD 12
#define DHC   64

// ---------------- scratch (no dynamic allocation allowed) ----------------
__device__ float g_Q[NSEG * HIDC];
__device__ float g_K[NSEG * HIDC];
__device__ float g_V[NSEG * HIDC];
__device__ float g_logits[E_TOT * NHEAD];
__device__ int   g_relCount[NRELC];
__device__ int   g_relOff[NRELC + 1];
__device__ int   g_relCur[NRELC];
__device__ int   g_segCount[NSEG];
__device__ int   g_segOff[NSEG + 1];
__device__ int   g_segCur[NSEG];
__device__ int   g_relEdges[E_TOT];
__device__ int   g_segEdges[E_TOT];

// ---------------- init: zero counters ----------------
__global__ void init_kernel() {
    int t = blockIdx.x * blockDim.x + threadIdx.x;
    if (t < NRELC) { g_relCount[t] = 0; g_relCur[t] = 0; }
    if (t < NSEG)  { g_segCount[t] = 0; g_segCur[t] = 0; }
}

// ---------------- count edges per relation and per segment ----------------
__global__ void count_kernel(const int* __restrict__ EI) {
    int e = blockIdx.x * blockDim.x + threadIdx.x;
    if (e >= E_TOT) return;
    atomicAdd(&g_relCount[EI[3 * E_TOT + e]], 1);
    atomicAdd(&g_segCount[EI[e] * 512 + EI[E_TOT + e]], 1);
}

// ---------------- exclusive scans (seg: 2048 via block scan; rel: serial 64) ----------------
__global__ void scan_kernel() {
    __shared__ int sh[1024];
    int t = threadIdx.x;  // 1024 threads
    int c0 = g_segCount[2 * t], c1 = g_segCount[2 * t + 1];
    int pair = c0 + c1;
    sh[t] = pair;
    __syncthreads();
    for (int off = 1; off < 1024; off <<= 1) {
        int v = (t >= off) ? sh[t - off] : 0;
        __syncthreads();
        sh[t] += v;
        __syncthreads();
    }
    int incl = sh[t];
    int eoff = incl - pair;
    g_segOff[2 * t]     = eoff;
    g_segOff[2 * t + 1] = eoff + c0;
    if (t == 1023) g_segOff[NSEG] = incl;
    if (t == 0) {
        int acc = 0;
        for (int i = 0; i < NRELC; i++) { g_relOff[i] = acc; acc += g_relCount[i]; }
        g_relOff[NRELC] = acc;
    }
}

// ---------------- scatter edge ids into relation + segment CSR lists ----------------
__global__ void scatter_kernel(const int* __restrict__ EI) {
    int e = blockIdx.x * blockDim.x + threadIdx.x;
    if (e >= E_TOT) return;
    int r = EI[3 * E_TOT + e];
    int p = atomicAdd(&g_relCur[r], 1);
    g_relEdges[g_relOff[r] + p] = e;
    int s = EI[e] * 512 + EI[E_TOT + e];
    int q = atomicAdd(&g_segCur[s], 1);
    g_segEdges[g_segOff[s] + q] = e;
}

// ---------------- fused QKV GEMM: out = X @ W^T + b ----------------
// M=2048, N=768, K=768. blockIdx.z selects {Q,K,V}. 64x64 tile, BK=16, 256 thr, 4x4 microtile.
__global__ __launch_bounds__(256) void qkv_gemm(
    const float* __restrict__ X,
    const float* __restrict__ Wq, const float* __restrict__ bq,
    const float* __restrict__ Wk, const float* __restrict__ bk,
    const float* __restrict__ Wv, const float* __restrict__ bv)
{
    const float* W; const float* bias; float* out;
    if (blockIdx.z == 0)      { W = Wq; bias = bq; out = g_Q; }
    else if (blockIdx.z == 1) { W = Wk; bias = bk; out = g_K; }
    else                      { W = Wv; bias = bv; out = g_V; }

    __shared__ float As[16][64];
    __shared__ float Bs[16][64];
    int m0 = blockIdx.x * 64, n0 = blockIdx.y * 64;
    int tid = threadIdx.x;
    int tx = tid & 15, ty = tid >> 4;
    int lr = tid >> 2;          // 0..63 row in tile
    int lc = (tid & 3) * 4;     // k offset 0,4,8,12

    float acc[4][4];
#pragma unroll
    for (int i = 0; i < 4; i++)
#pragma unroll
        for (int j = 0; j < 4; j++) acc[i][j] = 0.f;

    for (int k0 = 0; k0 < HIDC; k0 += 16) {
        float4 a  = *(const float4*)&X[(m0 + lr) * HIDC + k0 + lc];
        float4 bw = *(const float4*)&W[(n0 + lr) * HIDC + k0 + lc];
        As[lc + 0][lr] = a.x;  As[lc + 1][lr] = a.y;
        As[lc + 2][lr] = a.z;  As[lc + 3][lr] = a.w;
        Bs[lc + 0][lr] = bw.x; Bs[lc + 1][lr] = bw.y;
        Bs[lc + 2][lr] = bw.z; Bs[lc + 3][lr] = bw.w;
        __syncthreads();
#pragma unroll
        for (int kk = 0; kk < 16; kk++) {
            float4 av  = *(const float4*)&As[kk][ty * 4];
            float4 bv4 = *(const float4*)&Bs[kk][tx * 4];
            float aa[4] = {av.x, av.y, av.z, av.w};
            float bb[4] = {bv4.x, bv4.y, bv4.z, bv4.w};
#pragma unroll
            for (int i = 0; i < 4; i++)
#pragma unroll
                for (int j = 0; j < 4; j++) acc[i][j] += aa[i] * bb[j];
        }
        __syncthreads();
    }
#pragma unroll
    for (int i = 0; i < 4; i++) {
        int row = m0 + ty * 4 + i;
        int col = n0 + tx * 4;
        float4 o;
        o.x = acc[i][0] + bias[col + 0];
        o.y = acc[i][1] + bias[col + 1];
        o.z = acc[i][2] + bias[col + 2];
        o.w = acc[i][3] + bias[col + 3];
        *(float4*)&out[row * HIDC + col] = o;
    }
}

// ---------------- edge logits: logit[e,h] = (Q_h^T R_r K_h) / 8 ----------------
// grid (NRELC, CHUNKS), 256 thr = 8 warps, 1 edge per warp per pass, R shared per block.
// smem: Rs[64][65] | Qs[8][64][16] (d-major, float4-swizzled) | Ks[8][768]
#define LOG_EPB 8
#define LOG_CHUNKS 192
__global__ __launch_bounds__(256) void logits_kernel(
    const float* __restrict__ rel_emb, const int* __restrict__ EI)
{
    extern __shared__ float sm[];
    float* Rs = sm;                    // 64*65 = 4160
    float* Qs = Rs + 64 * 65;          // 8*64*16 = 8192
    float* Ks = Qs + 8 * 64 * 16;      // 8*768  = 6144

    int r = blockIdx.x;
    int cnt = g_relCount[r];
    if ((int)(blockIdx.y * LOG_EPB) >= cnt) return;
    int tid = threadIdx.x, lane = tid & 31, w = tid >> 5;

    const float* Rg = rel_emb + r * 4096;
    for (int i = tid; i < 4096; i += 256)
        Rs[(i >> 6) * 65 + (i & 63)] = Rg[i];

    int base = g_relOff[r];

    for (int c = blockIdx.y * LOG_EPB; c < cnt; c += gridDim.y * LOG_EPB) {
        int myIdx = c + w;
        bool valid = (myIdx < cnt);
        int eid = 0, b = 0, hn = 0, tn = 0;
        if (valid) {
            eid = g_relEdges[base + myIdx];
            b  = EI[eid];
            hn = EI[E_TOT + eid];
            tn = EI[2 * E_TOT + eid];
        }
        __syncthreads();   // protect smem reuse (and cover initial R load)
        if (valid) {
            const float* qrow = g_Q + (b * 512 + hn) * HIDC;
            const float* krow = g_K + (b * 512 + tn) * HIDC;
            float4* Qs4 = (float4*)(Qs + w * 64 * 16);
#pragma unroll
            for (int half = 0; half < 2; half++) {
                int d = lane + half * 32;
#pragma unroll
                for (int h4 = 0; h4 < 3; h4++) {
                    float4 v;
                    v.x = qrow[(h4 * 4 + 0) * 64 + d];
                    v.y = qrow[(h4 * 4 + 1) * 64 + d];
                    v.z = qrow[(h4 * 4 + 2) * 64 + d];
                    v.w = qrow[(h4 * 4 + 3) * 64 + d];
                    Qs4[d * 4 + ((h4 + d) & 3)] = v;   // swizzled: conflict-free STS.128
                }
            }
            for (int i = lane; i < HIDC; i += 32) Ks[w * HIDC + i] = krow[i];
        }
        __syncthreads();
        if (valid) {
            float accL[NHEAD], accH[NHEAD];
#pragma unroll
            for (int h = 0; h < NHEAD; h++) { accL[h] = 0.f; accH[h] = 0.f; }
            const float4* Qs4 = (const float4*)(Qs + w * 64 * 16);
#pragma unroll 4
            for (int d = 0; d < 64; d++) {
                float rl = Rs[d * 65 + lane];
                float rh = Rs[d * 65 + lane + 32];
                float4 q0 = Qs4[d * 4 + ((0 + d) & 3)];
                float4 q1 = Qs4[d * 4 + ((1 + d) & 3)];
                float4 q2 = Qs4[d * 4 + ((2 + d) & 3)];
                float qv[NHEAD] = {q0.x, q0.y, q0.z, q0.w,
                                   q1.x, q1.y, q1.z, q1.w,
                                   q2.x, q2.y, q2.z, q2.w};
#pragma unroll
                for (int h = 0; h < NHEAD; h++) {
                    accL[h] += qv[h] * rl;
                    accH[h] += qv[h] * rh;
                }
            }
#pragma unroll
            for (int h = 0; h < NHEAD; h++) {
                float v = accL[h] * Ks[w * HIDC + h * 64 + lane]
                        + accH[h] * Ks[w * HIDC + h * 64 + lane + 32];
#pragma unroll
                for (int off = 16; off; off >>= 1)
                    v += __shfl_xor_sync(0xffffffffu, v, off);
                if (lane == 0) g_logits[eid * NHEAD + h] = v * 0.125f;
            }
        }
    }
}

// ---------------- per-segment softmax + V aggregation (deterministic order) ----------------
// one block per segment (b, head_node); 384 threads = 12 warps.
__global__ __launch_bounds__(384) void agg_kernel(
    const int* __restrict__ EI, float* __restrict__ out)
{
    __shared__ float ps[32 * NHEAD];
    __shared__ int   tnb[32];
    __shared__ float shm[NHEAD], shinv[NHEAD];

    int s = blockIdx.x;
    int base = g_segOff[s];
    int cnt  = g_segOff[s + 1] - base;
    int tid = threadIdx.x, lane = tid & 31, w = tid >> 5;

    if (w < NHEAD && cnt > 0) {
        float m = -1e30f;
        for (int i = lane; i < cnt; i += 32)
            m = fmaxf(m, g_logits[g_segEdges[base + i] * NHEAD + w]);
#pragma unroll
        for (int off = 16; off; off >>= 1)
            m = fmaxf(m, __shfl_xor_sync(0xffffffffu, m, off));
        float ssum = 0.f;
        for (int i = lane; i < cnt; i += 32)
            ssum += __expf(g_logits[g_segEdges[base + i] * NHEAD + w] - m);
#pragma unroll
        for (int off = 16; off; off >>= 1)
            ssum += __shfl_xor_sync(0xffffffffu, ssum, off);
        if (lane == 0) { shm[w] = m; shinv[w] = 1.0f / ssum; }
    }
    __syncthreads();

    float acc0 = 0.f, acc1 = 0.f;
    int h0 = tid >> 6;                 // flat0 = tid
    int f1 = tid + 384;
    int h1 = f1 >> 6;
    int bb = s >> 9;                   // batch = s / 512

    for (int c0 = 0; c0 < cnt; c0 += 32) {
        int nc = min(32, cnt - c0);
        for (int idx = tid; idx < nc * NHEAD; idx += 384) {
            int j = idx / NHEAD, h = idx - NHEAD * j;
            int e = g_segEdges[base + c0 + j];
            ps[j * NHEAD + h] = __expf(g_logits[e * NHEAD + h] - shm[h]) * shinv[h];
        }
        if (tid < nc) tnb[tid] = EI[2 * E_TOT + g_segEdges[base + c0 + tid]];
        __syncthreads();
        for (int j = 0; j < nc; j++) {
            const float* vrow = g_V + (bb * 512 + tnb[j]) * HIDC;
            acc0 += ps[j * NHEAD + h0] * vrow[tid];
            acc1 += ps[j * NHEAD + h1] * vrow[f1];
        }
        __syncthreads();
    }
    out[s * HIDC + tid] = acc0;
    out[s * HIDC + f1]  = acc1;
}

// ---------------- launch ----------------
extern "C" void kernel_launch(void* const* d_in, const int* in_sizes, int n_in,
                              void* d_out, int out_size)
{
    const float* X   = (const float*)d_in[0];
    const int*   EI  = (const int*)  d_in[1];
    const float* Wq  = (const float*)d_in[3];
    const float* bq  = (const float*)d_in[4];
    const float* Wk  = (const float*)d_in[5];
    const float* bk  = (const float*)d_in[6];
    const float* Wv  = (const float*)d_in[7];
    const float* bv  = (const float*)d_in[8];
    const float* rel = (const float*)d_in[9];
    float* out = (float*)d_out;

    const int smem_logits = (64 * 65 + 8 * 64 * 16 + 8 * HIDC) * (int)sizeof(float);
    cudaFuncSetAttribute(logits_kernel,
                         cudaFuncAttributeMaxDynamicSharedMemorySize, smem_logits);

    init_kernel<<<2, 1024>>>();
    count_kernel<<<E_TOT / 256, 256>>>(EI);
    scan_kernel<<<1, 1024>>>();
    scatter_kernel<<<E_TOT / 256, 256>>>(EI);
    qkv_gemm<<<dim3(NSEG / 64, HIDC / 64, 3), 256>>>(X, Wq, bq, Wk, bk, Wv, bv);
    logits_kernel<<<dim3(NRELC, LOG_CHUNKS), 256, smem_logits>>>(rel, EI);
    agg_kernel<<<NSEG, 384>>>(EI, out);
}

// round 8
// speedup vs baseline: 2.0176x; 2.0176x over previous
#include <cuda_runtime.h>
#include <math.h>

#define E_TOT 65536
#define NRELC 64
#define NSEG  2048      // B*N = 4*512
#define HIDC  768
#define NHEAD 12
#define DHC   64

// ---------------- scratch ----------------
__device__ float g_Q[NSEG * HIDC];
__device__ float g_K[NSEG * HIDC];
__device__ float g_V[NSEG * HIDC];
__device__ float g_logits[E_TOT * NHEAD];
__device__ int   g_relCount[NRELC];
__device__ int   g_relOff[NRELC + 1];
__device__ int   g_relCur[NRELC];
__device__ int   g_segCount[NSEG];
__device__ int   g_segOff[NSEG + 1];
__device__ int   g_segCur[NSEG];
__device__ int   g_relEdges[E_TOT];
__device__ int   g_segEdges[E_TOT];

// ---------------- helpers ----------------
__device__ __forceinline__ unsigned f2tf32(float x) {
    unsigned u;
    asm("cvt.rna.tf32.f32 %0, %1;" : "=r"(u) : "f"(x));
    return u;
}

__device__ __forceinline__ void mma_tf32(float* d, const unsigned* a, const unsigned* b) {
    asm volatile(
        "mma.sync.aligned.m16n8k8.row.col.f32.tf32.tf32.f32 "
        "{%0,%1,%2,%3},{%4,%5,%6,%7},{%8,%9},{%0,%1,%2,%3};\n"
        : "+f"(d[0]), "+f"(d[1]), "+f"(d[2]), "+f"(d[3])
        : "r"(a[0]), "r"(a[1]), "r"(a[2]), "r"(a[3]), "r"(b[0]), "r"(b[1]));
}

// ---------------- init ----------------
__global__ void init_kernel() {
    int t = blockIdx.x * blockDim.x + threadIdx.x;
    if (t < NRELC) { g_relCount[t] = 0; g_relCur[t] = 0; }
    if (t < NSEG)  { g_segCount[t] = 0; g_segCur[t] = 0; }
}

// ---------------- count ----------------
__global__ void count_kernel(const int* __restrict__ EI) {
    int e = blockIdx.x * blockDim.x + threadIdx.x;
    if (e >= E_TOT) return;
    atomicAdd(&g_relCount[EI[3 * E_TOT + e]], 1);
    atomicAdd(&g_segCount[EI[e] * 512 + EI[E_TOT + e]], 1);
}

// ---------------- scans ----------------
__global__ void scan_kernel() {
    __shared__ int sh[1024];
    int t = threadIdx.x;
    int c0 = g_segCount[2 * t], c1 = g_segCount[2 * t + 1];
    int pair = c0 + c1;
    sh[t] = pair;
    __syncthreads();
    for (int off = 1; off < 1024; off <<= 1) {
        int v = (t >= off) ? sh[t - off] : 0;
        __syncthreads();
        sh[t] += v;
        __syncthreads();
    }
    int incl = sh[t];
    int eoff = incl - pair;
    g_segOff[2 * t]     = eoff;
    g_segOff[2 * t + 1] = eoff + c0;
    if (t == 1023) g_segOff[NSEG] = incl;
    if (t == 0) {
        int acc = 0;
        for (int i = 0; i < NRELC; i++) { g_relOff[i] = acc; acc += g_relCount[i]; }
        g_relOff[NRELC] = acc;
    }
}

// ---------------- scatter ----------------
__global__ void scatter_kernel(const int* __restrict__ EI) {
    int e = blockIdx.x * blockDim.x + threadIdx.x;
    if (e >= E_TOT) return;
    int r = EI[3 * E_TOT + e];
    int p = atomicAdd(&g_relCur[r], 1);
    g_relEdges[g_relOff[r] + p] = e;
    int s = EI[e] * 512 + EI[E_TOT + e];
    int q = atomicAdd(&g_segCur[s], 1);
    g_segEdges[g_segOff[s] + q] = e;
}

// ---------------- QKV GEMM via tf32 tensor MMA ----------------
// C(2048x768) = X @ W^T + b.  Block tile 128x64, BK=32, 8 warps (4x2), warp 32x32.
// Fragment-major smem layout so every fragment load is a consecutive-lane LDS.32.
__global__ __launch_bounds__(256) void qkv_gemm_tc(
    const float* __restrict__ X,
    const float* __restrict__ Wq, const float* __restrict__ bq,
    const float* __restrict__ Wk, const float* __restrict__ bk,
    const float* __restrict__ Wv, const float* __restrict__ bv)
{
    const float* W; const float* bias; float* out;
    if (blockIdx.z == 0)      { W = Wq; bias = bq; out = g_Q; }
    else if (blockIdx.z == 1) { W = Wk; bias = bk; out = g_K; }
    else                      { W = Wv; bias = bv; out = g_V; }

    __shared__ unsigned As[32 * 132];  // 32 subtiles (16x8) padded to 132 floats
    __shared__ unsigned Bs[32 * 68];   // 32 subtiles (8x8)  padded to 68 floats

    int tid = threadIdx.x;
    int lane = tid & 31, w = tid >> 5;
    int wm = w >> 1, wn = w & 1;
    int m0 = blockIdx.x * 128, n0 = blockIdx.y * 64;

    float acc[2][4][4];
#pragma unroll
    for (int i = 0; i < 2; i++)
#pragma unroll
        for (int j = 0; j < 4; j++)
#pragma unroll
            for (int k = 0; k < 4; k++) acc[i][j][k] = 0.f;

    float4 aR[4], bR[2];

    // prefetch chunk 0
#pragma unroll
    for (int j = 0; j < 4; j++) {
        int f4 = tid + j * 256;
        int row = f4 >> 3, c = f4 & 7;
        aR[j] = *(const float4*)&X[(m0 + row) * HIDC + c * 4];
    }
#pragma unroll
    for (int j = 0; j < 2; j++) {
        int f4 = tid + j * 256;
        int n = f4 >> 3, c = f4 & 7;
        bR[j] = *(const float4*)&W[(n0 + n) * HIDC + c * 4];
    }

    for (int kc = 0; kc < 24; kc++) {
        // store staged regs (convert to tf32)
#pragma unroll
        for (int j = 0; j < 4; j++) {
            int f4 = tid + j * 256;
            int row = f4 >> 3, c = f4 & 7;
            int sm = (row >> 4) * 4 + (c >> 1);
            unsigned* p = &As[(sm * 33 + (c & 1) * 16 + (row & 15)) * 4];
            uint4 uv = make_uint4(f2tf32(aR[j].x), f2tf32(aR[j].y),
                                  f2tf32(aR[j].z), f2tf32(aR[j].w));
            *(uint4*)p = uv;
        }
#pragma unroll
        for (int j = 0; j < 2; j++) {
            int f4 = tid + j * 256;
            int n = f4 >> 3, c = f4 & 7;
            int sub = (n >> 3) * 4 + (c >> 1);
            unsigned* p = &Bs[(sub * 17 + (c & 1) * 8 + (n & 7)) * 4];
            uint4 uv = make_uint4(f2tf32(bR[j].x), f2tf32(bR[j].y),
                                  f2tf32(bR[j].z), f2tf32(bR[j].w));
            *(uint4*)p = uv;
        }
        __syncthreads();

        // prefetch next chunk while computing
        if (kc < 23) {
            int k0 = (kc + 1) * 32;
#pragma unroll
            for (int j = 0; j < 4; j++) {
                int f4 = tid + j * 256;
                int row = f4 >> 3, c = f4 & 7;
                aR[j] = *(const float4*)&X[(m0 + row) * HIDC + k0 + c * 4];
            }
#pragma unroll
            for (int j = 0; j < 2; j++) {
                int f4 = tid + j * 256;
                int n = f4 >> 3, c = f4 & 7;
                bR[j] = *(const float4*)&W[(n0 + n) * HIDC + k0 + c * 4];
            }
        }

#pragma unroll
        for (int ks = 0; ks < 4; ks++) {
            unsigned af[2][4];
#pragma unroll
            for (int mi = 0; mi < 2; mi++) {
                int ab = ((wm * 2 + mi) * 4 + ks) * 132 + lane;
                af[mi][0] = As[ab];      af[mi][1] = As[ab + 32];
                af[mi][2] = As[ab + 64]; af[mi][3] = As[ab + 96];
            }
#pragma unroll
            for (int nt = 0; nt < 4; nt++) {
                unsigned bf[2];
                int bb = ((wn * 4 + nt) * 4 + ks) * 68 + lane;
                bf[0] = Bs[bb]; bf[1] = Bs[bb + 32];
#pragma unroll
                for (int mi = 0; mi < 2; mi++)
                    mma_tf32(acc[mi][nt], af[mi], bf);
            }
        }
        __syncthreads();
    }

    int g = lane >> 2, t = lane & 3;
#pragma unroll
    for (int mi = 0; mi < 2; mi++) {
        int r0 = m0 + wm * 32 + mi * 16 + g;
#pragma unroll
        for (int nt = 0; nt < 4; nt++) {
            int col = n0 + wn * 32 + nt * 8 + t * 2;
            float b0 = __ldg(&bias[col]), b1 = __ldg(&bias[col + 1]);
            float2 v0 = make_float2(acc[mi][nt][0] + b0, acc[mi][nt][1] + b1);
            *(float2*)&out[r0 * HIDC + col] = v0;
            float2 v1 = make_float2(acc[mi][nt][2] + b0, acc[mi][nt][3] + b1);
            *(float2*)&out[(r0 + 8) * HIDC + col] = v1;
        }
    }
}

// ---------------- edge logits via tf32 MMA ----------------
// Per relation r: Qp = gathered-Q(96 x 64) @ R(64x64) via MMA, epilogue dot with K (fp32).
// Block: 192 thr (6 warps), 8 edges/pass = 96 M-rows = 6 m-tiles of 16x64.
#define LTE 8
#define LOG_NCH 32
#define KS_HSTRIDE 68
#define KS_ISTRIDE (12 * KS_HSTRIDE + 8)   // 824
#define QS_FLOATS (48 * 132)               // 6336
#define KS_FLOATS (LTE * KS_ISTRIDE)       // 6592
#define RS_FLOATS (64 * 68)                // 4352
#define LOG_SMEM ((QS_FLOATS + KS_FLOATS + RS_FLOATS) * 4)

__global__ __launch_bounds__(192) void logits_mma(
    const float* __restrict__ rel_emb, const int* __restrict__ EI)
{
    extern __shared__ float smx[];
    unsigned* Qs = (unsigned*)smx;
    float*    Ks = smx + QS_FLOATS;
    unsigned* Rs = (unsigned*)(smx + QS_FLOATS + KS_FLOATS);
    __shared__ int eids[LTE], qrow[LTE], krow[LTE];

    int r = blockIdx.x;
    int cnt = g_relCount[r];
    if ((int)(blockIdx.y * LTE) >= cnt) return;
    int base = g_relOff[r];
    int tid = threadIdx.x, lane = tid & 31, w = tid >> 5;

    // stage R once: fragment-major tf32 (B-operand layout)
    const float* Rg = rel_emb + r * 4096;
    for (int idx = tid; idx < 1024; idx += 192) {
        float4 v = *(const float4*)&Rg[idx * 4];
        int d = idx >> 4, kc0 = (idx & 15) * 4;
        int sub = (d >> 3) * 8 + (kc0 >> 3);
        int p0 = sub * 68 + ((d & 7) >> 2) * 32 + (d & 3);
        int nb = kc0 & 7;
        Rs[p0 + (nb + 0) * 4] = f2tf32(v.x);
        Rs[p0 + (nb + 1) * 4] = f2tf32(v.y);
        Rs[p0 + (nb + 2) * 4] = f2tf32(v.z);
        Rs[p0 + (nb + 3) * 4] = f2tf32(v.w);
    }

    int g = lane >> 2, t = lane & 3;
    int m0r = w * 16 + g, m1r = m0r + 8;
    int i0 = m0r / 12, h0 = m0r - i0 * 12;
    int i1 = m1r / 12, h1 = m1r - i1 * 12;

    for (int c = blockIdx.y * LTE; c < cnt; c += LOG_NCH * LTE) {
        __syncthreads();
        if (tid < LTE) {
            int il = min(c + tid, cnt - 1);
            int e = g_relEdges[base + il];
            eids[tid] = e;
            qrow[tid] = (EI[e] * 512 + EI[E_TOT + e]) * HIDC;
            krow[tid] = (EI[e] * 512 + EI[2 * E_TOT + e]) * HIDC;
        }
        __syncthreads();

        // stage Q (fragment-major tf32): 1536 float4, 8 per thread
#pragma unroll
        for (int j = 0; j < 8; j++) {
            int f4 = tid + j * 192;
            int m = f4 >> 4, dc = f4 & 15;
            int i = m / 12, h = m - i * 12;
            float4 v = *(const float4*)&g_Q[qrow[i] + h * 64 + dc * 4];
            int sm = (m >> 4) * 8 + (dc >> 1);
            unsigned* p = &Qs[(sm * 33 + (dc & 1) * 16 + (m & 15)) * 4];
            uint4 uv = make_uint4(f2tf32(v.x), f2tf32(v.y), f2tf32(v.z), f2tf32(v.w));
            *(uint4*)p = uv;
        }
        // stage K rows (fp32), padded strides for bank spread
#pragma unroll
        for (int j = 0; j < 8; j++) {
            int h = tid >> 4;               // tid*4 / 64
            int d = (tid & 15) * 4;
            float4 v = *(const float4*)&g_K[krow[j] + tid * 4];
            *(float4*)&Ks[j * KS_ISTRIDE + h * KS_HSTRIDE + d] = v;
        }
        __syncthreads();

        // MMA: warp w owns m-tile w (16 rows x 64 cols)
        float acc[8][4];
#pragma unroll
        for (int nt = 0; nt < 8; nt++)
#pragma unroll
            for (int k = 0; k < 4; k++) acc[nt][k] = 0.f;

#pragma unroll
        for (int ks = 0; ks < 8; ks++) {
            unsigned af[4];
            int ab = (w * 8 + ks) * 132 + lane;
            af[0] = Qs[ab];      af[1] = Qs[ab + 32];
            af[2] = Qs[ab + 64]; af[3] = Qs[ab + 96];
#pragma unroll
            for (int nt = 0; nt < 8; nt++) {
                unsigned bf[2];
                int bb = (ks * 8 + nt) * 68 + lane;
                bf[0] = Rs[bb]; bf[1] = Rs[bb + 32];
                mma_tf32(acc[nt], af, bf);
            }
        }

        // epilogue: dot Qp rows with K rows (fp32), reduce over 4-lane group
        float p0 = 0.f, p1 = 0.f;
        const float* k0p = &Ks[i0 * KS_ISTRIDE + h0 * KS_HSTRIDE];
        const float* k1p = &Ks[i1 * KS_ISTRIDE + h1 * KS_HSTRIDE];
#pragma unroll
        for (int nt = 0; nt < 8; nt++) {
            int col = nt * 8 + t * 2;
            float2 ka = *(const float2*)&k0p[col];
            float2 kb = *(const float2*)&k1p[col];
            p0 += acc[nt][0] * ka.x + acc[nt][1] * ka.y;
            p1 += acc[nt][2] * kb.x + acc[nt][3] * kb.y;
        }
        p0 += __shfl_xor_sync(0xffffffffu, p0, 1);
        p0 += __shfl_xor_sync(0xffffffffu, p0, 2);
        p1 += __shfl_xor_sync(0xffffffffu, p1, 1);
        p1 += __shfl_xor_sync(0xffffffffu, p1, 2);
        if (t == 0) {
            if (c + i0 < cnt) g_logits[eids[i0] * NHEAD + h0] = p0 * 0.125f;
            if (c + i1 < cnt) g_logits[eids[i1] * NHEAD + h1] = p1 * 0.125f;
        }
    }
}

// ---------------- per-segment softmax + V aggregation ----------------
__global__ __launch_bounds__(384) void agg_kernel(
    const int* __restrict__ EI, float* __restrict__ out)
{
    __shared__ float ps[32 * NHEAD];
    __shared__ int   tnb[32];
    __shared__ float shm[NHEAD], shinv[NHEAD];

    int s = blockIdx.x;
    int base = g_segOff[s];
    int cnt  = g_segOff[s + 1] - base;
    int tid = threadIdx.x, lane = tid & 31, w = tid >> 5;

    if (w < NHEAD && cnt > 0) {
        float m = -1e30f;
        for (int i = lane; i < cnt; i += 32)
            m = fmaxf(m, g_logits[g_segEdges[base + i] * NHEAD + w]);
#pragma unroll
        for (int off = 16; off; off >>= 1)
            m = fmaxf(m, __shfl_xor_sync(0xffffffffu, m, off));
        float ssum = 0.f;
        for (int i = lane; i < cnt; i += 32)
            ssum += __expf(g_logits[g_segEdges[base + i] * NHEAD + w] - m);
#pragma unroll
        for (int off = 16; off; off >>= 1)
            ssum += __shfl_xor_sync(0xffffffffu, ssum, off);
        if (lane == 0) { shm[w] = m; shinv[w] = 1.0f / ssum; }
    }
    __syncthreads();

    float acc0 = 0.f, acc1 = 0.f;
    int h0 = tid >> 6;
    int f1 = tid + 384;
    int h1 = f1 >> 6;
    int bb = s >> 9;

    for (int c0 = 0; c0 < cnt; c0 += 32) {
        int nc = min(32, cnt - c0);
        for (int idx = tid; idx < nc * NHEAD; idx += 384) {
            int j = idx / NHEAD, h = idx - NHEAD * j;
            int e = g_segEdges[base + c0 + j];
            ps[j * NHEAD + h] = __expf(g_logits[e * NHEAD + h] - shm[h]) * shinv[h];
        }
        if (tid < nc) tnb[tid] = EI[2 * E_TOT + g_segEdges[base + c0 + tid]];
        __syncthreads();
        for (int j = 0; j < nc; j++) {
            const float* vrow = g_V + (bb * 512 + tnb[j]) * HIDC;
            acc0 += ps[j * NHEAD + h0] * vrow[tid];
            acc1 += ps[j * NHEAD + h1] * vrow[f1];
        }
        __syncthreads();
    }
    out[s * HIDC + tid] = acc0;
    out[s * HIDC + f1]  = acc1;
}

// ---------------- launch ----------------
extern "C" void kernel_launch(void* const* d_in, const int* in_sizes, int n_in,
                              void* d_out, int out_size)
{
    const float* X   = (const float*)d_in[0];
    const int*   EI  = (const int*)  d_in[1];
    const float* Wq  = (const float*)d_in[3];
    const float* bq  = (const float*)d_in[4];
    const float* Wk  = (const float*)d_in[5];
    const float* bk  = (const float*)d_in[6];
    const float* Wv  = (const float*)d_in[7];
    const float* bv  = (const float*)d_in[8];
    const float* rel = (const float*)d_in[9];
    float* out = (float*)d_out;

    cudaFuncSetAttribute(logits_mma,
                         cudaFuncAttributeMaxDynamicSharedMemorySize, LOG_SMEM);

    init_kernel<<<2, 1024>>>();
    count_kernel<<<E_TOT / 256, 256>>>(EI);
    scan_kernel<<<1, 1024>>>();
    scatter_kernel<<<E_TOT / 256, 256>>>(EI);
    qkv_gemm_tc<<<dim3(2048 / 128, 768 / 64, 3), 256>>>(X, Wq, bq, Wk, bk, Wv, bv);
    logits_mma<<<dim3(NRELC, LOG_NCH), 192, LOG_SMEM>>>(rel, EI);
    agg_kernel<<<NSEG, 384>>>(EI, out);
}

// round 9
// speedup vs baseline: 2.6834x; 1.3300x over previous
#include <cuda_runtime.h>
#include <math.h>

#define E_TOT 65536
#define NRELC 64
#define NSEG  2048      // B*N = 4*512
#define HIDC  768
#define NHEAD 12
#define DHC   64

// ---------------- scratch ----------------
__device__ float g_Q[NSEG * HIDC];
__device__ float g_K[NSEG * HIDC];
__device__ float g_V[NSEG * HIDC];
__device__ float g_logits[E_TOT * NHEAD];
__device__ int   g_relCount[NRELC];
__device__ int   g_relOff[NRELC + 1];
__device__ int   g_relCur[NRELC];
__device__ int   g_segCount[NSEG];
__device__ int   g_segOff[NSEG + 1];
__device__ int   g_segCur[NSEG];
__device__ int   g_relEdges[E_TOT];
__device__ int   g_segEdges[E_TOT];

// generational grid barrier state (monotonic across graph replays — no reset needed)
__device__ unsigned g_ticket;
__device__ unsigned g_release;

#define PREP_BLOCKS 128
#define PREP_THREADS 512

__device__ __forceinline__ void grid_bar() {
    __syncthreads();
    if (threadIdx.x == 0) {
        __threadfence();
        unsigned t = atomicAdd(&g_ticket, 1u);
        unsigned gen = t / PREP_BLOCKS;
        if ((t % PREP_BLOCKS) == PREP_BLOCKS - 1)
            atomicAdd(&g_release, 1u);
        while (*(volatile unsigned*)&g_release <= gen) { }
        __threadfence();
    }
    __syncthreads();
}

// ---------------- helpers ----------------
__device__ __forceinline__ unsigned f2tf32(float x) {
    unsigned u;
    asm("cvt.rna.tf32.f32 %0, %1;" : "=r"(u) : "f"(x));
    return u;
}

__device__ __forceinline__ void mma_tf32(float* d, const unsigned* a, const unsigned* b) {
    asm volatile(
        "mma.sync.aligned.m16n8k8.row.col.f32.tf32.tf32.f32 "
        "{%0,%1,%2,%3},{%4,%5,%6,%7},{%8,%9},{%0,%1,%2,%3};\n"
        : "+f"(d[0]), "+f"(d[1]), "+f"(d[2]), "+f"(d[3])
        : "r"(a[0]), "r"(a[1]), "r"(a[2]), "r"(a[3]), "r"(b[0]), "r"(b[1]));
}

// ---------------- fused prep: zero -> count -> scan -> scatter ----------------
__global__ __launch_bounds__(PREP_THREADS) void prep_kernel(const int* __restrict__ EI)
{
    __shared__ int hrel[NRELC];
    __shared__ int hbase[NRELC];
    __shared__ int sh2[PREP_THREADS];

    int tid = threadIdx.x, bid = blockIdx.x;
    int e = bid * PREP_THREADS + tid;          // exactly covers E_TOT

    // ---- phase 0: zero counters ----
    if (bid == 0 && tid < NRELC) { g_relCount[tid] = 0; g_relCur[tid] = 0; }
    if (bid < 4) { g_segCount[bid * 512 + tid] = 0; g_segCur[bid * 512 + tid] = 0; }
    grid_bar();

    // ---- phase 1: count (rel privatized in smem; seg direct: 32 ops/addr) ----
    if (tid < NRELC) hrel[tid] = 0;
    __syncthreads();
    int r = EI[3 * E_TOT + e];
    int s = EI[e] * 512 + EI[E_TOT + e];
    atomicAdd(&hrel[r], 1);
    atomicAdd(&g_segCount[s], 1);
    __syncthreads();
    if (tid < NRELC && hrel[tid] != 0) atomicAdd(&g_relCount[tid], hrel[tid]);
    grid_bar();

    // ---- phase 2: scans (block 0 only) ----
    if (bid == 0) {
        int a0 = g_segCount[tid * 4 + 0], a1 = g_segCount[tid * 4 + 1];
        int a2 = g_segCount[tid * 4 + 2], a3 = g_segCount[tid * 4 + 3];
        int sum = a0 + a1 + a2 + a3;
        sh2[tid] = sum;
        __syncthreads();
        for (int off = 1; off < PREP_THREADS; off <<= 1) {
            int v = (tid >= off) ? sh2[tid - off] : 0;
            __syncthreads();
            sh2[tid] += v;
            __syncthreads();
        }
        int excl = sh2[tid] - sum;
        g_segOff[tid * 4 + 0] = excl;
        g_segOff[tid * 4 + 1] = excl + a0;
        g_segOff[tid * 4 + 2] = excl + a0 + a1;
        g_segOff[tid * 4 + 3] = excl + a0 + a1 + a2;
        if (tid == PREP_THREADS - 1) g_segOff[NSEG] = sh2[tid];
        if (tid == 0) {
            int acc = 0;
            for (int i = 0; i < NRELC; i++) { g_relOff[i] = acc; acc += g_relCount[i]; }
            g_relOff[NRELC] = acc;
        }
    }
    grid_bar();

    // ---- phase 3: scatter (rel block-privatized rank + one claim per (block,rel)) ----
    if (tid < NRELC) hrel[tid] = 0;
    __syncthreads();
    int lrank = atomicAdd(&hrel[r], 1);
    __syncthreads();
    if (tid < NRELC) {
        int c = hrel[tid];
        hbase[tid] = c ? atomicAdd(&g_relCur[tid], c) : 0;
    }
    __syncthreads();
    g_relEdges[g_relOff[r] + hbase[r] + lrank] = e;
    int q = atomicAdd(&g_segCur[s], 1);
    g_segEdges[g_segOff[s] + q] = e;
}

// ---------------- QKV GEMM via tf32 tensor MMA ----------------
__global__ __launch_bounds__(256) void qkv_gemm_tc(
    const float* __restrict__ X,
    const float* __restrict__ Wq, const float* __restrict__ bq,
    const float* __restrict__ Wk, const float* __restrict__ bk,
    const float* __restrict__ Wv, const float* __restrict__ bv)
{
    const float* W; const float* bias; float* out;
    if (blockIdx.z == 0)      { W = Wq; bias = bq; out = g_Q; }
    else if (blockIdx.z == 1) { W = Wk; bias = bk; out = g_K; }
    else                      { W = Wv; bias = bv; out = g_V; }

    __shared__ unsigned As[32 * 132];
    __shared__ unsigned Bs[32 * 68];

    int tid = threadIdx.x;
    int lane = tid & 31, w = tid >> 5;
    int wm = w >> 1, wn = w & 1;
    int m0 = blockIdx.x * 128, n0 = blockIdx.y * 64;

    float acc[2][4][4];
#pragma unroll
    for (int i = 0; i < 2; i++)
#pragma unroll
        for (int j = 0; j < 4; j++)
#pragma unroll
            for (int k = 0; k < 4; k++) acc[i][j][k] = 0.f;

    float4 aR[4], bR[2];

#pragma unroll
    for (int j = 0; j < 4; j++) {
        int f4 = tid + j * 256;
        int row = f4 >> 3, c = f4 & 7;
        aR[j] = *(const float4*)&X[(m0 + row) * HIDC + c * 4];
    }
#pragma unroll
    for (int j = 0; j < 2; j++) {
        int f4 = tid + j * 256;
        int n = f4 >> 3, c = f4 & 7;
        bR[j] = *(const float4*)&W[(n0 + n) * HIDC + c * 4];
    }

    for (int kc = 0; kc < 24; kc++) {
#pragma unroll
        for (int j = 0; j < 4; j++) {
            int f4 = tid + j * 256;
            int row = f4 >> 3, c = f4 & 7;
            int sm = (row >> 4) * 4 + (c >> 1);
            unsigned* p = &As[(sm * 33 + (c & 1) * 16 + (row & 15)) * 4];
            uint4 uv = make_uint4(f2tf32(aR[j].x), f2tf32(aR[j].y),
                                  f2tf32(aR[j].z), f2tf32(aR[j].w));
            *(uint4*)p = uv;
        }
#pragma unroll
        for (int j = 0; j < 2; j++) {
            int f4 = tid + j * 256;
            int n = f4 >> 3, c = f4 & 7;
            int sub = (n >> 3) * 4 + (c >> 1);
            unsigned* p = &Bs[(sub * 17 + (c & 1) * 8 + (n & 7)) * 4];
            uint4 uv = make_uint4(f2tf32(bR[j].x), f2tf32(bR[j].y),
                                  f2tf32(bR[j].z), f2tf32(bR[j].w));
            *(uint4*)p = uv;
        }
        __syncthreads();

        if (kc < 23) {
            int k0 = (kc + 1) * 32;
#pragma unroll
            for (int j = 0; j < 4; j++) {
                int f4 = tid + j * 256;
                int row = f4 >> 3, c = f4 & 7;
                aR[j] = *(const float4*)&X[(m0 + row) * HIDC + k0 + c * 4];
            }
#pragma unroll
            for (int j = 0; j < 2; j++) {
                int f4 = tid + j * 256;
                int n = f4 >> 3, c = f4 & 7;
                bR[j] = *(const float4*)&W[(n0 + n) * HIDC + k0 + c * 4];
            }
        }

#pragma unroll
        for (int ks = 0; ks < 4; ks++) {
            unsigned af[2][4];
#pragma unroll
            for (int mi = 0; mi < 2; mi++) {
                int ab = ((wm * 2 + mi) * 4 + ks) * 132 + lane;
                af[mi][0] = As[ab];      af[mi][1] = As[ab + 32];
                af[mi][2] = As[ab + 64]; af[mi][3] = As[ab + 96];
            }
#pragma unroll
            for (int nt = 0; nt < 4; nt++) {
                unsigned bf[2];
                int bb = ((wn * 4 + nt) * 4 + ks) * 68 + lane;
                bf[0] = Bs[bb]; bf[1] = Bs[bb + 32];
#pragma unroll
                for (int mi = 0; mi < 2; mi++)
                    mma_tf32(acc[mi][nt], af[mi], bf);
            }
        }
        __syncthreads();
    }

    int g = lane >> 2, t = lane & 3;
#pragma unroll
    for (int mi = 0; mi < 2; mi++) {
        int r0 = m0 + wm * 32 + mi * 16 + g;
#pragma unroll
        for (int nt = 0; nt < 4; nt++) {
            int col = n0 + wn * 32 + nt * 8 + t * 2;
            float b0 = __ldg(&bias[col]), b1 = __ldg(&bias[col + 1]);
            float2 v0 = make_float2(acc[mi][nt][0] + b0, acc[mi][nt][1] + b1);
            *(float2*)&out[r0 * HIDC + col] = v0;
            float2 v1 = make_float2(acc[mi][nt][2] + b0, acc[mi][nt][3] + b1);
            *(float2*)&out[(r0 + 8) * HIDC + col] = v1;
        }
    }
}

// ---------------- edge logits via tf32 MMA (K read direct from L2, no smem staging) ----------------
#define LTE 8
#define LOG_NCH 32
#define QS_FLOATS (48 * 132)               // 6336
#define RS_FLOATS (64 * 68)                // 4352
#define LOG_SMEM ((QS_FLOATS + RS_FLOATS) * 4)

__global__ __launch_bounds__(192) void logits_mma(
    const float* __restrict__ rel_emb, const int* __restrict__ EI)
{
    extern __shared__ float smx[];
    unsigned* Qs = (unsigned*)smx;
    unsigned* Rs = (unsigned*)(smx + QS_FLOATS);
    __shared__ int eids[LTE], qrow[LTE], krow[LTE];

    int r = blockIdx.x;
    int cnt = g_relCount[r];
    if ((int)(blockIdx.y * LTE) >= cnt) return;
    int base = g_relOff[r];
    int tid = threadIdx.x, lane = tid & 31, w = tid >> 5;

    // stage R once: fragment-major tf32 (B-operand layout)
    const float* Rg = rel_emb + r * 4096;
    for (int idx = tid; idx < 1024; idx += 192) {
        float4 v = *(const float4*)&Rg[idx * 4];
        int d = idx >> 4, kc0 = (idx & 15) * 4;
        int sub = (d >> 3) * 8 + (kc0 >> 3);
        int p0 = sub * 68 + ((d & 7) >> 2) * 32 + (d & 3);
        int nb = kc0 & 7;
        Rs[p0 + (nb + 0) * 4] = f2tf32(v.x);
        Rs[p0 + (nb + 1) * 4] = f2tf32(v.y);
        Rs[p0 + (nb + 2) * 4] = f2tf32(v.z);
        Rs[p0 + (nb + 3) * 4] = f2tf32(v.w);
    }

    int g = lane >> 2, t = lane & 3;
    int m0r = w * 16 + g, m1r = m0r + 8;
    int i0 = m0r / 12, h0 = m0r - i0 * 12;
    int i1 = m1r / 12, h1 = m1r - i1 * 12;

    for (int c = blockIdx.y * LTE; c < cnt; c += LOG_NCH * LTE) {
        __syncthreads();
        if (tid < LTE) {
            int il = min(c + tid, cnt - 1);
            int e = g_relEdges[base + il];
            eids[tid] = e;
            qrow[tid] = (EI[e] * 512 + EI[E_TOT + e]) * HIDC;
            krow[tid] = (EI[e] * 512 + EI[2 * E_TOT + e]) * HIDC;
        }
        __syncthreads();

        // stage Q (fragment-major tf32): 1536 float4, 8 per thread
#pragma unroll
        for (int j = 0; j < 8; j++) {
            int f4 = tid + j * 192;
            int m = f4 >> 4, dc = f4 & 15;
            int i = m / 12, h = m - i * 12;
            float4 v = *(const float4*)&g_Q[qrow[i] + h * 64 + dc * 4];
            int sm = (m >> 4) * 8 + (dc >> 1);
            unsigned* p = &Qs[(sm * 33 + (dc & 1) * 16 + (m & 15)) * 4];
            uint4 uv = make_uint4(f2tf32(v.x), f2tf32(v.y), f2tf32(v.z), f2tf32(v.w));
            *(uint4*)p = uv;
        }
        __syncthreads();

        // MMA: warp w owns m-tile w (16 rows x 64 cols)
        float acc[8][4];
#pragma unroll
        for (int nt = 0; nt < 8; nt++)
#pragma unroll
            for (int k = 0; k < 4; k++) acc[nt][k] = 0.f;

#pragma unroll
        for (int ks = 0; ks < 8; ks++) {
            unsigned af[4];
            int ab = (w * 8 + ks) * 132 + lane;
            af[0] = Qs[ab];      af[1] = Qs[ab + 32];
            af[2] = Qs[ab + 64]; af[3] = Qs[ab + 96];
#pragma unroll
            for (int nt = 0; nt < 8; nt++) {
                unsigned bf[2];
                int bb = (ks * 8 + nt) * 68 + lane;
                bf[0] = Rs[bb]; bf[1] = Rs[bb + 32];
                mma_tf32(acc[nt], af, bf);
            }
        }

        // epilogue: dot Qp rows with K rows straight from L2 (each K element used once)
        float p0 = 0.f, p1 = 0.f;
        const float* k0p = &g_K[krow[i0] + h0 * 64];
        const float* k1p = &g_K[krow[i1] + h1 * 64];
#pragma unroll
        for (int nt = 0; nt < 8; nt++) {
            int col = nt * 8 + t * 2;
            float2 ka = *(const float2*)&k0p[col];
            float2 kb = *(const float2*)&k1p[col];
            p0 += acc[nt][0] * ka.x + acc[nt][1] * ka.y;
            p1 += acc[nt][2] * kb.x + acc[nt][3] * kb.y;
        }
        p0 += __shfl_xor_sync(0xffffffffu, p0, 1);
        p0 += __shfl_xor_sync(0xffffffffu, p0, 2);
        p1 += __shfl_xor_sync(0xffffffffu, p1, 1);
        p1 += __shfl_xor_sync(0xffffffffu, p1, 2);
        if (t == 0) {
            if (c + i0 < cnt) g_logits[eids[i0] * NHEAD + h0] = p0 * 0.125f;
            if (c + i1 < cnt) g_logits[eids[i1] * NHEAD + h1] = p1 * 0.125f;
        }
    }
}

// ---------------- per-segment softmax + V aggregation ----------------
#define AGG_CAP 128
__global__ __launch_bounds__(384) void agg_kernel(
    const int* __restrict__ EI, float* __restrict__ out)
{
    __shared__ float lg[AGG_CAP * 13];
    __shared__ int   tnb2[AGG_CAP];
    __shared__ float shm[NHEAD], shinv[NHEAD];
    __shared__ float ps[32 * NHEAD];
    __shared__ int   tnb[32];

    int s = blockIdx.x;
    int base = g_segOff[s];
    int cnt  = g_segOff[s + 1] - base;
    int tid = threadIdx.x, lane = tid & 31, w = tid >> 5;
    int bb = s >> 9;
    int h0 = tid >> 6;
    int f1 = tid + 384;
    int h1 = f1 >> 6;
    float acc0 = 0.f, acc1 = 0.f;

    if (cnt == 0) {
        out[s * HIDC + tid] = 0.f;
        out[s * HIDC + f1] = 0.f;
        return;
    }

    if (cnt <= AGG_CAP) {
        // one global pass: cache logits (pad-13 rows: conflict-free) + tail ids
        for (int idx = tid; idx < cnt * NHEAD; idx += 384) {
            int j = idx / NHEAD, h = idx - NHEAD * j;
            int e = g_segEdges[base + j];
            lg[j * 13 + h] = g_logits[e * NHEAD + h];
            if (h == 0) tnb2[j] = EI[2 * E_TOT + e];
        }
        __syncthreads();
        if (w < NHEAD) {
            float m = -1e30f;
            for (int i = lane; i < cnt; i += 32) m = fmaxf(m, lg[i * 13 + w]);
#pragma unroll
            for (int off = 16; off; off >>= 1)
                m = fmaxf(m, __shfl_xor_sync(0xffffffffu, m, off));
            float ss = 0.f;
            for (int i = lane; i < cnt; i += 32) ss += __expf(lg[i * 13 + w] - m);
#pragma unroll
            for (int off = 16; off; off >>= 1)
                ss += __shfl_xor_sync(0xffffffffu, ss, off);
            if (lane == 0) { shm[w] = m; shinv[w] = 1.0f / ss; }
        }
        __syncthreads();
        // exp-normalize in place, once
        for (int idx = tid; idx < cnt * NHEAD; idx += 384) {
            int j = idx / NHEAD, h = idx - NHEAD * j;
            lg[j * 13 + h] = __expf(lg[j * 13 + h] - shm[h]) * shinv[h];
        }
        __syncthreads();
        // V aggregation: no syncs inside, independent loads -> high MLP
        for (int j = 0; j < cnt; j++) {
            const float* vrow = g_V + (bb * 512 + tnb2[j]) * HIDC;
            acc0 += lg[j * 13 + h0] * vrow[tid];
            acc1 += lg[j * 13 + h1] * vrow[f1];
        }
    } else {
        // streaming fallback (rare / safety)
        if (w < NHEAD) {
            float m = -1e30f;
            for (int i = lane; i < cnt; i += 32)
                m = fmaxf(m, g_logits[g_segEdges[base + i] * NHEAD + w]);
#pragma unroll
            for (int off = 16; off; off >>= 1)
                m = fmaxf(m, __shfl_xor_sync(0xffffffffu, m, off));
            float ssum = 0.f;
            for (int i = lane; i < cnt; i += 32)
                ssum += __expf(g_logits[g_segEdges[base + i] * NHEAD + w] - m);
#pragma unroll
            for (int off = 16; off; off >>= 1)
                ssum += __shfl_xor_sync(0xffffffffu, ssum, off);
            if (lane == 0) { shm[w] = m; shinv[w] = 1.0f / ssum; }
        }
        __syncthreads();
        for (int c0 = 0; c0 < cnt; c0 += 32) {
            int nc = min(32, cnt - c0);
            for (int idx = tid; idx < nc * NHEAD; idx += 384) {
                int j = idx / NHEAD, h = idx - NHEAD * j;
                int e = g_segEdges[base + c0 + j];
                ps[j * NHEAD + h] = __expf(g_logits[e * NHEAD + h] - shm[h]) * shinv[h];
            }
            if (tid < nc) tnb[tid] = EI[2 * E_TOT + g_segEdges[base + c0 + tid]];
            __syncthreads();
            for (int j = 0; j < nc; j++) {
                const float* vrow = g_V + (bb * 512 + tnb[j]) * HIDC;
                acc0 += ps[j * NHEAD + h0] * vrow[tid];
                acc1 += ps[j * NHEAD + h1] * vrow[f1];
            }
            __syncthreads();
        }
    }
    out[s * HIDC + tid] = acc0;
    out[s * HIDC + f1]  = acc1;
}

// ---------------- launch ----------------
extern "C" void kernel_launch(void* const* d_in, const int* in_sizes, int n_in,
                              void* d_out, int out_size)
{
    const float* X   = (const float*)d_in[0];
    const int*   EI  = (const int*)  d_in[1];
    const float* Wq  = (const float*)d_in[3];
    const float* bq  = (const float*)d_in[4];
    const float* Wk  = (const float*)d_in[5];
    const float* bk  = (const float*)d_in[6];
    const float* Wv  = (const float*)d_in[7];
    const float* bv  = (const float*)d_in[8];
    const float* rel = (const float*)d_in[9];
    float* out = (float*)d_out;

    prep_kernel<<<PREP_BLOCKS, PREP_THREADS>>>(EI);
    qkv_gemm_tc<<<dim3(2048 / 128, 768 / 64, 3), 256>>>(X, Wq, bq, Wk, bk, Wv, bv);
    logits_mma<<<dim3(NRELC, LOG_NCH), 192, LOG_SMEM>>>(rel, EI);
    agg_kernel<<<NSEG, 384>>>(EI, out);
}